// round 8
// baseline (speedup 1.0000x reference)
#include <cuda_runtime.h>

// StandardPershomReadout — packed f32x2, combined division (1 MUFU / 2 pairs),
// 32-reg occupancy, single-kernel graph (scratch + last-block drain).
// f(d) = 1/(1+d) - 1/(1+||r|-d|) = (b-a)/(a*b),  a=1+d, b=1+|u|, u=d-|r|.

#define KC    64
#define TPB   128               // 4 warps; forced 32 regs -> 16 blocks/SM
#define PTS   128               // points per tile
#define PPT   (PTS / 4)         // 32 points per warp
#define NT0   (128 * (4096 / PTS))   // 4096 sec0 tiles (32 chunks per b)
#define NTE   (128 * (1024 / PTS))   // 1024 tiles per ess section (8 chunks per b)
#define NTILES (NT0 + 2 * NTE)       // 6144

typedef unsigned long long ull;

__device__ float        g_scratch[128 * 3 * KC];   // zero-init at load; re-zeroed by drain
__device__ unsigned int g_count[128 * 3];          // zero-init; reset by last block

#define ADD2(o,a,b)   asm("add.rn.f32x2 %0, %1, %2;" : "=l"(o) : "l"(a), "l"(b))
#define MUL2(o,a,b)   asm("mul.rn.f32x2 %0, %1, %2;" : "=l"(o) : "l"(a), "l"(b))
#define FMA2(o,a,b,c) asm("fma.rn.f32x2 %0, %1, %2, %3;" : "=l"(o) : "l"(a), "l"(b), "l"(c))
#define ABS2(o,a)     asm("and.b64 %0, %1, 0x7FFFFFFF7FFFFFFF;" : "=l"(o) : "l"(a))

__device__ __forceinline__ ull pk2(float lo, float hi) {
    ull r; asm("mov.b64 %0, {%1, %2};" : "=l"(r) : "f"(lo), "f"(hi)); return r;
}
__device__ __forceinline__ void upk2(ull v, float& lo, float& hi) {
    asm("mov.b64 {%0, %1}, %2;" : "=f"(lo), "=f"(hi) : "l"(v));
}
__device__ __forceinline__ float frcp(float x) {
    float r; asm("rcp.approx.ftz.f32 %0, %1;" : "=f"(r) : "f"(x)); return r;
}

// one center, one packed point-pair; combined division: 1 MUFU per call.
__device__ __forceinline__ void hat_accum(ull d2, ull m2, ull nar2, ull one2, ull negone2,
                                          float& acc)
{
    ull u2, a2, b2, den2, num2, nm2;
    ADD2(u2, d2, nar2);  ABS2(u2, u2);      // |d - |r||
    ADD2(a2, d2, one2);                     // 1 + d
    ADD2(b2, u2, one2);                     // 1 + |u|
    MUL2(den2, a2, b2);
    FMA2(num2, a2, negone2, b2);            // b - a  ==  |u| - d
    MUL2(nm2, num2, m2);
    float dl, dh, nl, nh;
    upk2(den2, dl, dh); upk2(nm2, nl, nh);
    float dd = dl * dh;
    float nn = fmaf(nl, dh, nh * dl);       // nl*dh + nh*dl
    acc = fmaf(nn, frcp(dd), acc);          // (nl/dl + nh/dh)
}

__global__ void __launch_bounds__(TPB, 16)
pershom_kernel(const float* __restrict__ h0,  const float* __restrict__ m0,
               const float* __restrict__ h0e, const float* __restrict__ m0e,
               const float* __restrict__ h1e, const float* __restrict__ m1e,
               const float* __restrict__ c0,  const float* __restrict__ r0,
               const float* __restrict__ c0e, const float* __restrict__ r0e,
               const float* __restrict__ c1e, const float* __restrict__ r1e,
               float* __restrict__ out)
{
    __shared__ __align__(16) float sxx[PTS];
    __shared__ __align__(16) float syy[PTS];
    __shared__ __align__(16) float smm[PTS];
    __shared__ float red[KC];
    __shared__ unsigned int slast;

    const int t   = blockIdx.x;
    const int tid = threadIdx.x;

    int b, dim, grp, nchunks, outoff;
    const float *pts, *mask, *centers, *radp;

    if (t < NT0) {
        b = t >> 5; int chunk = t & 31;
        dim = 2; grp = b; nchunks = 32; outoff = 0;
        pts  = h0 + ((size_t)b * 4096 + chunk * PTS) * 2;
        mask = m0 + (size_t)b * 4096 + chunk * PTS;
        centers = c0; radp = r0;
    } else if (t < NT0 + NTE) {
        int r = t - NT0;
        b = r >> 3; int chunk = r & 7;
        dim = 1; grp = 128 + b; nchunks = 8; outoff = KC;
        pts  = h0e + (size_t)b * 1024 + chunk * PTS;
        mask = m0e + (size_t)b * 1024 + chunk * PTS;
        centers = c0e; radp = r0e;
    } else {
        int r = t - NT0 - NTE;
        b = r >> 3; int chunk = r & 7;
        dim = 1; grp = 256 + b; nchunks = 8; outoff = 2 * KC;
        pts  = h1e + (size_t)b * 1024 + chunk * PTS;
        mask = m1e + (size_t)b * 1024 + chunk * PTS;
        centers = c1e; radp = r1e;
    }
    // scratch/out offset for this group
    const int gbase = b * (3 * KC) + outoff;

    // Stage SoA (one element per thread at PTS==TPB).
    if (dim == 2) {
        float2 v = ((const float2*)pts)[tid];
        sxx[tid] = v.x; syy[tid] = v.y;
    } else {
        sxx[tid] = pts[tid];
    }
    smm[tid] = mask[tid];
    if (tid < KC) red[tid] = 0.0f;

    const int lane = tid & 31;
    const int team = tid >> 5;               // 4 warp-teams
    const float ar = fabsf(*radp);

    const ull one2    = pk2(1.0f, 1.0f);
    const ull negone2 = pk2(-1.0f, -1.0f);
    const ull nar2    = pk2(-ar, -ar);

    ull ncxA, ncyA = 0, ncxB, ncyB = 0;
    if (dim == 2) {
        float cax = centers[2 * lane],        cay = centers[2 * lane + 1];
        float cbx = centers[2 * (lane + 32)], cby = centers[2 * (lane + 32) + 1];
        ncxA = pk2(-cax, -cax); ncyA = pk2(-cay, -cay);
        ncxB = pk2(-cbx, -cbx); ncyB = pk2(-cby, -cby);
    } else {
        float ca = centers[lane], cb = centers[lane + 32];
        ncxA = pk2(-ca, -ca);
        ncxB = pk2(-cb, -cb);
    }

    __syncthreads();

    float accA = 0.0f, accB = 0.0f;
    const int base = team * PPT;

    if (dim == 2) {
        #pragma unroll 2
        for (int i = 0; i < PPT; i += 2) {
            const ull p2x = *(const ull*)&sxx[base + i];
            const ull p2y = *(const ull*)&syy[base + i];
            const ull m2  = *(const ull*)&smm[base + i];
            ull tx, ty, d2;
            // center A
            ADD2(tx, p2x, ncxA); ABS2(tx, tx);
            ADD2(ty, p2y, ncyA); ABS2(ty, ty);
            ADD2(d2, tx, ty);
            hat_accum(d2, m2, nar2, one2, negone2, accA);
            // center B
            ADD2(tx, p2x, ncxB); ABS2(tx, tx);
            ADD2(ty, p2y, ncyB); ABS2(ty, ty);
            ADD2(d2, tx, ty);
            hat_accum(d2, m2, nar2, one2, negone2, accB);
        }
    } else {
        #pragma unroll 2
        for (int i = 0; i < PPT; i += 2) {
            const ull p2x = *(const ull*)&sxx[base + i];
            const ull m2  = *(const ull*)&smm[base + i];
            ull tx;
            ADD2(tx, p2x, ncxA); ABS2(tx, tx);
            hat_accum(tx, m2, nar2, one2, negone2, accA);
            ADD2(tx, p2x, ncxB); ABS2(tx, tx);
            hat_accum(tx, m2, nar2, one2, negone2, accB);
        }
    }

    // Block reduce: per-warp lanes hit distinct smem addresses (no conflict).
    atomicAdd(&red[lane],      accA);
    atomicAdd(&red[lane + 32], accB);
    __syncthreads();

    // Push partial into global scratch (zero at replay start by construction).
    if (tid < KC)
        atomicAdd(&g_scratch[gbase + tid], red[tid]);
    __threadfence();
    __syncthreads();
    if (tid == 0) {
        unsigned int old = atomicAdd(&g_count[grp], 1u);
        slast = (old == (unsigned int)(nchunks - 1)) ? 1u : 0u;
    }
    __syncthreads();

    if (slast) {
        // Last block of the group: drain scratch (re-zeroing it for the next
        // replay via atomicExch), write final output, reset the counter.
        if (tid < KC) {
            float v = atomicExch(&g_scratch[gbase + tid], 0.0f);
            out[gbase + tid] = v;
        }
        if (tid == 0) g_count[grp] = 0u;
    }
}

extern "C" void kernel_launch(void* const* d_in, const int* in_sizes, int n_in,
                              void* d_out, int out_size)
{
    (void)in_sizes; (void)n_in; (void)out_size;
    const float* h0  = (const float*)d_in[0];
    const float* m0  = (const float*)d_in[1];
    const float* h0e = (const float*)d_in[2];
    const float* m0e = (const float*)d_in[3];
    const float* h1e = (const float*)d_in[4];
    const float* m1e = (const float*)d_in[5];
    const float* c0  = (const float*)d_in[6];
    const float* r0  = (const float*)d_in[7];
    const float* c0e = (const float*)d_in[8];
    const float* r0e = (const float*)d_in[9];
    const float* c1e = (const float*)d_in[10];
    const float* r1e = (const float*)d_in[11];
    float* out = (float*)d_out;

    pershom_kernel<<<NTILES, TPB>>>(h0, m0, h0e, m0e, h1e, m1e,
                                    c0, r0, c0e, r0e, c1e, r1e, out);
}